// round 1
// baseline (speedup 1.0000x reference)
#include <cuda_runtime.h>
#include <cuda_bf16.h>
#include <cstdint>

// ---------------- problem constants ----------------
#define NB    4          // batch
#define DIM   128        // per-head dim (= D)
#define HEADS 8
#define PPTS  12544      // patches total (112*112)
#define CWID  112        // patch grid width
#define WIN   7
#define NWX   16         // windows per axis
#define WN    256        // windows per image
#define PT    49         // tokens per window

// qkv scratch: [3][NB][HEADS][WN][PT][DIM]
#define QKV_STRIDE ((size_t)NB * HEADS * WN * PT * DIM)   // 51,380,224 floats
__device__ float g_qkv[3 * NB * HEADS * WN * PT * DIM];
// merged attention output: [NB][HEADS*DIM][PPTS]
__device__ float g_mid[(size_t)NB * HEADS * DIM * PPTS];

// ---------------- Kernel A: QKV projection + window partition ----------------
// C[o,p] = sum_d W[o,d] * x[n,d,p] + b[o], o in [0,1024), p in [0,12544)
// Tile 64x64, BK=16, 256 threads, 4x4 per thread.
__global__ void qkv_kernel(const float* __restrict__ x,
                           const float* __restrict__ Wq, const float* __restrict__ bq,
                           const float* __restrict__ Wk, const float* __restrict__ bk,
                           const float* __restrict__ Wv, const float* __restrict__ bv) {
    int z = blockIdx.z;           // 0..11
    int n = z & 3;
    int which = z >> 2;           // 0=q,1=k,2=v
    const float* W = (which == 0) ? Wq : (which == 1) ? Wk : Wv;
    const float* b = (which == 0) ? bq : (which == 1) ? bk : bv;
    float* dst = g_qkv + (size_t)which * QKV_STRIDE;

    __shared__ float Ws[16][64];      // [k][o]
    __shared__ float Xs[16][64];      // [k][p]

    int tid = threadIdx.x;
    int tx = tid & 15, ty = tid >> 4;
    int o0 = blockIdx.y * 64 + ty * 4;
    int p0 = blockIdx.x * 64 + tx * 4;
    const float* xn = x + (size_t)n * DIM * PPTS;

    float acc[4][4] = {};

    for (int k0 = 0; k0 < 128; k0 += 16) {
        // load W tile: 64(o) x 16(k), coalesced along k
        #pragma unroll
        for (int i = 0; i < 4; i++) {
            int f = tid * 4 + i;
            int r = f >> 4, c = f & 15;
            Ws[c][r] = W[(size_t)(blockIdx.y * 64 + r) * 128 + k0 + c];
        }
        // load X tile: 16(k) x 64(p), coalesced along p
        #pragma unroll
        for (int i = 0; i < 4; i++) {
            int f = tid + i * 256;
            int r = f >> 6, c = f & 63;
            Xs[r][c] = xn[(size_t)(k0 + r) * PPTS + blockIdx.x * 64 + c];
        }
        __syncthreads();
        #pragma unroll
        for (int kk = 0; kk < 16; kk++) {
            float a[4], bb[4];
            #pragma unroll
            for (int i = 0; i < 4; i++) a[i] = Ws[kk][ty * 4 + i];
            #pragma unroll
            for (int j = 0; j < 4; j++) bb[j] = Xs[kk][tx * 4 + j];
            #pragma unroll
            for (int i = 0; i < 4; i++)
                #pragma unroll
                for (int j = 0; j < 4; j++)
                    acc[i][j] += a[i] * bb[j];
        }
        __syncthreads();
    }

    // epilogue: write to window-partitioned layout [n][h][win][tok][d]
    #pragma unroll
    for (int i = 0; i < 4; i++) {
        int o = o0 + i;
        int hh = o >> 7, d = o & 127;
        float bias = b[o];
        #pragma unroll
        for (int j = 0; j < 4; j++) {
            int p = p0 + j;
            int prow = p / CWID, pcol = p % CWID;
            int win = (prow / WIN) * NWX + (pcol / WIN);
            int tok = (prow % WIN) * WIN + (pcol % WIN);
            dst[((((size_t)n * HEADS + hh) * WN + win) * PT + tok) * DIM + d] = acc[i][j] + bias;
        }
    }
}

// ---------------- Kernel B: windowed attention ----------------
// One block per (n, h, window). k,q,v staged in smem as [tok][d].
// S[j][i] = (k_i . q_j)/sqrt(D) + bias(h,i,j); softmax over i per column j;
// out[d][j] = sum_i v[i][d] * S[j][i]  -> written to g_mid[n][h*128+d][p]
__global__ void attn_kernel(const float* __restrict__ pos_code) {
    extern __shared__ float sm[];
    float* sk = sm;                    // 49*128
    float* sq = sk + PT * DIM;         // 49*128
    float* sv = sq + PT * DIM;         // 49*128
    float* S  = sv + PT * DIM;         // 49*49
    float* sb = S + PT * PT;           // 169

    int bid = blockIdx.x;
    int w = bid & 255;
    int h = (bid >> 8) & 7;
    int n = bid >> 11;
    int tid = threadIdx.x;

    const size_t winoff = (((size_t)n * HEADS + h) * WN + w) * (PT * DIM);
    const float4* gq = (const float4*)(g_qkv + winoff);
    const float4* gk = (const float4*)(g_qkv + QKV_STRIDE + winoff);
    const float4* gv = (const float4*)(g_qkv + 2 * QKV_STRIDE + winoff);

    for (int i = tid; i < PT * DIM / 4; i += 256) {
        ((float4*)sq)[i] = gq[i];
        ((float4*)sk)[i] = gk[i];
        ((float4*)sv)[i] = gv[i];
    }
    for (int i = tid; i < 169; i += 256) sb[i] = pos_code[i * HEADS + h];
    __syncthreads();

    const float scale = 0.08838834764831845f;  // 1/sqrt(128)
    for (int idx = tid; idx < PT * PT; idx += 256) {
        int j = idx / PT, i = idx - j * PT;
        const float4* ki = (const float4*)(sk + i * DIM);
        const float4* qj = (const float4*)(sq + j * DIM);
        float acc = 0.f;
        #pragma unroll
        for (int d4 = 0; d4 < DIM / 4; d4++) {
            float4 a = ki[d4], c = qj[d4];
            acc += a.x * c.x + a.y * c.y + a.z * c.z + a.w * c.w;
        }
        int yi = i / WIN, xi = i - yi * WIN;
        int yj = j / WIN, xj = j - yj * WIN;
        int ridx = (yi - yj + WIN - 1) + (xi - xj + WIN - 1) * (2 * WIN - 1);
        S[j * PT + i] = acc * scale + sb[ridx];
    }
    __syncthreads();

    if (tid < PT) {
        float* row = S + tid * PT;
        float m = -1e30f;
        #pragma unroll
        for (int i = 0; i < PT; i++) m = fmaxf(m, row[i]);
        float s = 0.f;
        #pragma unroll
        for (int i = 0; i < PT; i++) { float e = __expf(row[i] - m); row[i] = e; s += e; }
        float inv = 1.f / s;
        #pragma unroll
        for (int i = 0; i < PT; i++) row[i] *= inv;
    }
    __syncthreads();

    int wy = w >> 4, wx = w & 15;
    for (int idx = tid; idx < DIM * PT; idx += 256) {
        int d = idx / PT, j = idx - d * PT;
        float acc = 0.f;
        for (int i = 0; i < PT; i++)
            acc += sv[i * DIM + d] * S[j * PT + i];
        int jy = j / WIN, jx = j - jy * WIN;
        int p = (wy * WIN + jy) * CWID + wx * WIN + jx;
        g_mid[((size_t)n * (HEADS * DIM) + h * DIM + d) * PPTS + p] = acc;
    }
}

// ---------------- Kernel C: output projection ----------------
// out[n,o,p] = sum_c Wo[o,c] * mid[n,c,p] + bo[o], o<128, c<1024
__global__ void out_kernel(const float* __restrict__ Wo, const float* __restrict__ bo,
                           float* __restrict__ out) {
    int n = blockIdx.z;
    __shared__ float Ws[16][64];
    __shared__ float Xs[16][64];

    int tid = threadIdx.x;
    int tx = tid & 15, ty = tid >> 4;
    int o0 = blockIdx.y * 64 + ty * 4;
    int p0 = blockIdx.x * 64 + tx * 4;
    const float* mid = g_mid + (size_t)n * (HEADS * DIM) * PPTS;

    float acc[4][4] = {};

    for (int k0 = 0; k0 < 1024; k0 += 16) {
        #pragma unroll
        for (int i = 0; i < 4; i++) {
            int f = tid * 4 + i;
            int r = f >> 4, c = f & 15;
            Ws[c][r] = Wo[(size_t)(blockIdx.y * 64 + r) * 1024 + k0 + c];
        }
        #pragma unroll
        for (int i = 0; i < 4; i++) {
            int f = tid + i * 256;
            int r = f >> 6, c = f & 63;
            Xs[r][c] = mid[(size_t)(k0 + r) * PPTS + blockIdx.x * 64 + c];
        }
        __syncthreads();
        #pragma unroll
        for (int kk = 0; kk < 16; kk++) {
            float a[4], bb[4];
            #pragma unroll
            for (int i = 0; i < 4; i++) a[i] = Ws[kk][ty * 4 + i];
            #pragma unroll
            for (int j = 0; j < 4; j++) bb[j] = Xs[kk][tx * 4 + j];
            #pragma unroll
            for (int i = 0; i < 4; i++)
                #pragma unroll
                for (int j = 0; j < 4; j++)
                    acc[i][j] += a[i] * bb[j];
        }
        __syncthreads();
    }

    #pragma unroll
    for (int i = 0; i < 4; i++) {
        int o = o0 + i;
        float bias = bo[o];
        #pragma unroll
        for (int j = 0; j < 4; j++) {
            int p = p0 + j;
            out[((size_t)n * DIM + o) * PPTS + p] = acc[i][j] + bias;
        }
    }
}

// ---------------- launch ----------------
extern "C" void kernel_launch(void* const* d_in, const int* in_sizes, int n_in,
                              void* d_out, int out_size) {
    const float* x   = (const float*)d_in[0];
    const float* Wq  = (const float*)d_in[1];
    const float* bq  = (const float*)d_in[2];
    const float* Wk  = (const float*)d_in[3];
    const float* bk  = (const float*)d_in[4];
    const float* Wv  = (const float*)d_in[5];
    const float* bv  = (const float*)d_in[6];
    const float* Wo  = (const float*)d_in[7];
    const float* bo  = (const float*)d_in[8];
    const float* pos = (const float*)d_in[9];
    float* out = (float*)d_out;

    // Kernel A: QKV projection + partition
    {
        dim3 grid(PPTS / 64, 1024 / 64, 12);   // (196, 16, 12)
        qkv_kernel<<<grid, 256>>>(x, Wq, bq, Wk, bk, Wv, bv);
    }

    // Kernel B: attention
    {
        const int smem = (3 * PT * DIM + PT * PT + 169) * (int)sizeof(float); // 85544 B
        static int attr_set = 0;
        if (!attr_set) {
            cudaFuncSetAttribute(attn_kernel, cudaFuncAttributeMaxDynamicSharedMemorySize, smem);
            attr_set = 1;
        }
        attn_kernel<<<NB * HEADS * WN, 256, smem>>>(pos);
    }

    // Kernel C: output projection
    {
        dim3 grid(PPTS / 64, 128 / 64, NB);    // (196, 2, 4)
        out_kernel<<<grid, 256>>>(Wo, bo, out);
    }
}

// round 2
// speedup vs baseline: 2.2949x; 2.2949x over previous
#include <cuda_runtime.h>
#include <cuda_bf16.h>
#include <cstdint>

// ---------------- problem constants ----------------
#define NB    4
#define DIM   128
#define HEADS 8
#define PPTS  12544
#define CWID  112
#define WIN   7
#define NWX   16
#define WN    256
#define PT    49
#define SROW  132          // padded smem row stride (floats) for attn tiles

#define QKV_STRIDE ((size_t)NB * HEADS * WN * PT * DIM)
__device__ float g_qkv[3 * NB * HEADS * WN * PT * DIM];
__device__ float g_mid[(size_t)NB * HEADS * DIM * PPTS];

// ---------------- Kernel A: QKV projection + window partition ----------------
// 128x128 tile, BK=8, 256 threads, 8x8 per thread.
__global__ __launch_bounds__(256, 2)
void qkv_kernel(const float* __restrict__ x,
                const float* __restrict__ Wq, const float* __restrict__ bq,
                const float* __restrict__ Wk, const float* __restrict__ bk,
                const float* __restrict__ Wv, const float* __restrict__ bv) {
    int z = blockIdx.z;
    int n = z & 3;
    int which = z >> 2;
    const float* W = (which == 0) ? Wq : (which == 1) ? Wk : Wv;
    const float* b = (which == 0) ? bq : (which == 1) ? bk : bv;
    float* dst = g_qkv + (size_t)which * QKV_STRIDE;

    __shared__ float As[8][128];   // [k][o]
    __shared__ float Bs[8][128];   // [k][p]

    int tid = threadIdx.x;
    int tx = tid & 15, ty = tid >> 4;
    int o_base = blockIdx.y * 128;        // == h*128
    int p_base = blockIdx.x * 128;
    const float* xn = x + (size_t)n * DIM * PPTS;

    float acc[8][8] = {};

    int arow = tid >> 1, akq = (tid & 1) << 2;     // W load: row 0..127, k-quad
    int brow = tid >> 5, bcol = (tid & 31) << 2;   // x load: row 0..7, col-quad

    for (int k0 = 0; k0 < 128; k0 += 8) {
        float4 wv4 = *(const float4*)&W[(size_t)(o_base + arow) * 128 + k0 + akq];
        As[akq + 0][arow] = wv4.x;
        As[akq + 1][arow] = wv4.y;
        As[akq + 2][arow] = wv4.z;
        As[akq + 3][arow] = wv4.w;
        *(float4*)&Bs[brow][bcol] = *(const float4*)&xn[(size_t)(k0 + brow) * PPTS + p_base + bcol];
        __syncthreads();
        #pragma unroll
        for (int kk = 0; kk < 8; kk++) {
            float4 a0 = *(const float4*)&As[kk][ty * 8];
            float4 a1 = *(const float4*)&As[kk][ty * 8 + 4];
            float4 b0 = *(const float4*)&Bs[kk][tx * 8];
            float4 b1 = *(const float4*)&Bs[kk][tx * 8 + 4];
            float a[8] = {a0.x, a0.y, a0.z, a0.w, a1.x, a1.y, a1.z, a1.w};
            float bb[8] = {b0.x, b0.y, b0.z, b0.w, b1.x, b1.y, b1.z, b1.w};
            #pragma unroll
            for (int i = 0; i < 8; i++)
                #pragma unroll
                for (int j = 0; j < 8; j++)
                    acc[i][j] += a[i] * bb[j];
        }
        __syncthreads();
    }

    int h = blockIdx.y;        // 128 outputs per head
    int d0 = ty * 8;
    float bias[8];
    #pragma unroll
    for (int i = 0; i < 8; i++) bias[i] = b[o_base + d0 + i];

    #pragma unroll
    for (int j = 0; j < 8; j++) {
        int p = p_base + tx * 8 + j;
        int prow = p / CWID, pcol = p - prow * CWID;
        int win = (prow / WIN) * NWX + (pcol / WIN);
        int tok = (prow % WIN) * WIN + (pcol % WIN);
        float* o = dst + ((((size_t)n * HEADS + h) * WN + win) * PT + tok) * DIM + d0;
        float4 v0 = make_float4(acc[0][j] + bias[0], acc[1][j] + bias[1],
                                acc[2][j] + bias[2], acc[3][j] + bias[3]);
        float4 v1 = make_float4(acc[4][j] + bias[4], acc[5][j] + bias[5],
                                acc[6][j] + bias[6], acc[7][j] + bias[7]);
        *(float4*)o = v0;
        *(float4*)(o + 4) = v1;
    }
}

// ---------------- Kernel B: windowed attention ----------------
__global__ __launch_bounds__(256, 2)
void attn_kernel(const float* __restrict__ pos_code) {
    extern __shared__ float sm[];
    float* sq = sm;                     // 49 rows x SROW
    float* sk = sq + PT * SROW;
    float* sv = sk + PT * SROW;
    float* S  = sv + PT * SROW;         // 49*49
    float* sb = S + PT * PT;            // 169

    int bid = blockIdx.x;
    int w = bid & 255;
    int h = (bid >> 8) & 7;
    int n = bid >> 11;
    int tid = threadIdx.x;

    const size_t winoff = (((size_t)n * HEADS + h) * WN + w) * (PT * DIM);
    const float4* gq = (const float4*)(g_qkv + winoff);
    const float4* gk = (const float4*)(g_qkv + QKV_STRIDE + winoff);
    const float4* gv = (const float4*)(g_qkv + 2 * QKV_STRIDE + winoff);

    for (int i = tid; i < PT * 32; i += 256) {
        int r = i >> 5, c = i & 31;
        ((float4*)(sq + r * SROW))[c] = gq[i];
        ((float4*)(sk + r * SROW))[c] = gk[i];
        ((float4*)(sv + r * SROW))[c] = gv[i];
    }
    for (int i = tid; i < 169; i += 256) sb[i] = pos_code[i * HEADS + h];
    __syncthreads();

    // ---- S[j][i] = (k_i . q_j) * scale + bias, 4x4 register tiles ----
    const float scale = 0.08838834764831845f;
    for (int t = tid; t < 169; t += 256) {
        int tj = t / 13, ti = t - tj * 13;
        int j0 = tj * 4, i0 = ti * 4;
        const float4* qr[4];
        const float4* kr[4];
        #pragma unroll
        for (int u = 0; u < 4; u++) {
            qr[u] = (const float4*)(sq + min(j0 + u, PT - 1) * SROW);
            kr[u] = (const float4*)(sk + min(i0 + u, PT - 1) * SROW);
        }
        float acc[4][4] = {};
        #pragma unroll 8
        for (int d4 = 0; d4 < 32; d4++) {
            float4 qv[4], kv[4];
            #pragma unroll
            for (int u = 0; u < 4; u++) { qv[u] = qr[u][d4]; kv[u] = kr[u][d4]; }
            #pragma unroll
            for (int jj = 0; jj < 4; jj++)
                #pragma unroll
                for (int ii = 0; ii < 4; ii++)
                    acc[jj][ii] += qv[jj].x * kv[ii].x + qv[jj].y * kv[ii].y
                                 + qv[jj].z * kv[ii].z + qv[jj].w * kv[ii].w;
        }
        #pragma unroll
        for (int jj = 0; jj < 4; jj++) {
            int j = j0 + jj;
            if (j >= PT) break;
            int yj = j / WIN, xj = j - yj * WIN;
            #pragma unroll
            for (int ii = 0; ii < 4; ii++) {
                int i = i0 + ii;
                if (i >= PT) break;
                int yi = i / WIN, xi = i - yi * WIN;
                int ridx = (yi - yj + WIN - 1) + (xi - xj + WIN - 1) * (2 * WIN - 1);
                S[j * PT + i] = acc[jj][ii] * scale + sb[ridx];
            }
        }
    }
    __syncthreads();

    // ---- softmax over i, one thread per column j ----
    if (tid < PT) {
        float* row = S + tid * PT;
        float m = -1e30f;
        #pragma unroll
        for (int i = 0; i < PT; i++) m = fmaxf(m, row[i]);
        float s = 0.f;
        #pragma unroll
        for (int i = 0; i < PT; i++) { float e = __expf(row[i] - m); row[i] = e; s += e; }
        float inv = 1.f / s;
        #pragma unroll
        for (int i = 0; i < PT; i++) row[i] *= inv;
    }
    __syncthreads();

    // ---- out[d][j] = sum_i v[i][d] * P[j][i], 4d x 4j per thread ----
    int wy = w >> 4, wx = w & 15;
    float* mid = g_mid + ((size_t)n * (HEADS * DIM) + h * DIM) * PPTS;
    for (int t = tid; t < 13 * 32; t += 256) {
        int jq = t >> 5, dq = t & 31;      // dq: float4 index along d, jq: 4 j's
        int j0 = jq * 4;
        float4 a0 = make_float4(0.f, 0.f, 0.f, 0.f), a1 = a0, a2 = a0, a3 = a0;
        int j1 = min(j0 + 1, PT - 1), j2 = min(j0 + 2, PT - 1), j3 = min(j0 + 3, PT - 1);
        #pragma unroll 7
        for (int i = 0; i < PT; i++) {
            float4 vv = ((const float4*)(sv + i * SROW))[dq];
            float p0 = S[j0 * PT + i], p1 = S[j1 * PT + i];
            float p2 = S[j2 * PT + i], p3 = S[j3 * PT + i];
            a0.x += vv.x * p0; a0.y += vv.y * p0; a0.z += vv.z * p0; a0.w += vv.w * p0;
            a1.x += vv.x * p1; a1.y += vv.y * p1; a1.z += vv.z * p1; a1.w += vv.w * p1;
            a2.x += vv.x * p2; a2.y += vv.y * p2; a2.z += vv.z * p2; a2.w += vv.w * p2;
            a3.x += vv.x * p3; a3.y += vv.y * p3; a3.z += vv.z * p3; a3.w += vv.w * p3;
        }
        float4 accs[4] = {a0, a1, a2, a3};
        int d0 = dq * 4;
        #pragma unroll
        for (int jj = 0; jj < 4; jj++) {
            int j = j0 + jj;
            if (j >= PT) break;
            int jy = j / WIN, jx = j - jy * WIN;
            int p = (wy * WIN + jy) * CWID + wx * WIN + jx;
            mid[(size_t)(d0 + 0) * PPTS + p] = accs[jj].x;
            mid[(size_t)(d0 + 1) * PPTS + p] = accs[jj].y;
            mid[(size_t)(d0 + 2) * PPTS + p] = accs[jj].z;
            mid[(size_t)(d0 + 3) * PPTS + p] = accs[jj].w;
        }
    }
}

// ---------------- Kernel C: output projection ----------------
// out[n,o,p] = sum_c Wo[o,c] * mid[n,c,p] + bo[o]; o<128, c<1024
__global__ __launch_bounds__(256, 2)
void out_kernel(const float* __restrict__ Wo, const float* __restrict__ bo,
                float* __restrict__ out) {
    int n = blockIdx.z;
    __shared__ float As[8][128];
    __shared__ float Bs[8][128];

    int tid = threadIdx.x;
    int tx = tid & 15, ty = tid >> 4;
    int p_base = blockIdx.x * 128;
    const float* mid = g_mid + (size_t)n * (HEADS * DIM) * PPTS;

    float acc[8][8] = {};
    int arow = tid >> 1, akq = (tid & 1) << 2;
    int brow = tid >> 5, bcol = (tid & 31) << 2;

    for (int k0 = 0; k0 < 1024; k0 += 8) {
        float4 wv4 = *(const float4*)&Wo[(size_t)arow * 1024 + k0 + akq];
        As[akq + 0][arow] = wv4.x;
        As[akq + 1][arow] = wv4.y;
        As[akq + 2][arow] = wv4.z;
        As[akq + 3][arow] = wv4.w;
        *(float4*)&Bs[brow][bcol] = *(const float4*)&mid[(size_t)(k0 + brow) * PPTS + p_base + bcol];
        __syncthreads();
        #pragma unroll
        for (int kk = 0; kk < 8; kk++) {
            float4 a0 = *(const float4*)&As[kk][ty * 8];
            float4 a1 = *(const float4*)&As[kk][ty * 8 + 4];
            float4 b0 = *(const float4*)&Bs[kk][tx * 8];
            float4 b1 = *(const float4*)&Bs[kk][tx * 8 + 4];
            float a[8] = {a0.x, a0.y, a0.z, a0.w, a1.x, a1.y, a1.z, a1.w};
            float bb[8] = {b0.x, b0.y, b0.z, b0.w, b1.x, b1.y, b1.z, b1.w};
            #pragma unroll
            for (int i = 0; i < 8; i++)
                #pragma unroll
                for (int j = 0; j < 8; j++)
                    acc[i][j] += a[i] * bb[j];
        }
        __syncthreads();
    }

    #pragma unroll
    for (int i = 0; i < 8; i++) {
        int o = ty * 8 + i;
        float bias = bo[o];
        float* dst = out + ((size_t)n * DIM + o) * PPTS + p_base + tx * 8;
        float4 v0 = make_float4(acc[i][0] + bias, acc[i][1] + bias,
                                acc[i][2] + bias, acc[i][3] + bias);
        float4 v1 = make_float4(acc[i][4] + bias, acc[i][5] + bias,
                                acc[i][6] + bias, acc[i][7] + bias);
        *(float4*)dst = v0;
        *(float4*)(dst + 4) = v1;
    }
}

// ---------------- launch ----------------
extern "C" void kernel_launch(void* const* d_in, const int* in_sizes, int n_in,
                              void* d_out, int out_size) {
    const float* x   = (const float*)d_in[0];
    const float* Wq  = (const float*)d_in[1];
    const float* bq  = (const float*)d_in[2];
    const float* Wk  = (const float*)d_in[3];
    const float* bk  = (const float*)d_in[4];
    const float* Wv  = (const float*)d_in[5];
    const float* bv  = (const float*)d_in[6];
    const float* Wo  = (const float*)d_in[7];
    const float* bo  = (const float*)d_in[8];
    const float* pos = (const float*)d_in[9];
    float* out = (float*)d_out;

    {
        dim3 grid(PPTS / 128, 1024 / 128, 12);   // (98, 8, 12)
        qkv_kernel<<<grid, 256>>>(x, Wq, bq, Wk, bk, Wv, bv);
    }
    {
        const int smem = (3 * PT * SROW + PT * PT + 169) * (int)sizeof(float);
        static int attr_set = 0;
        if (!attr_set) {
            cudaFuncSetAttribute(attn_kernel, cudaFuncAttributeMaxDynamicSharedMemorySize, smem);
            attr_set = 1;
        }
        attn_kernel<<<NB * HEADS * WN, 256, smem>>>(pos);
    }
    {
        dim3 grid(PPTS / 128, 1, NB);
        out_kernel<<<grid, 256>>>(Wo, bo, out);
    }
}

// round 3
// speedup vs baseline: 3.6667x; 1.5978x over previous
#include <cuda_runtime.h>
#include <cuda_bf16.h>
#include <cstdint>

// ---------------- problem constants ----------------
#define NB    4
#define DIM   128
#define HEADS 8
#define PPTS  12544
#define CWID  112
#define WIN   7
#define NWX   16
#define WN    256
#define PT    49
#define PTP   52           // padded token count (gmem + smem) for q/k transposed layout

// q,k transposed: [n][h][win][d=128][PTP];  v: [n][h][win][tok=49][128]
__device__ float g_q[(size_t)NB * HEADS * WN * DIM * PTP];
__device__ float g_k[(size_t)NB * HEADS * WN * DIM * PTP];
__device__ float g_v[(size_t)NB * HEADS * WN * PT * DIM];
__device__ float g_mid[(size_t)NB * HEADS * DIM * PPTS];

__device__ __forceinline__ float tf32f(float x) {
    uint32_t u;
    asm("cvt.rna.tf32.f32 %0, %1;" : "=r"(u) : "f"(x));
    return __uint_as_float(u);
}

__device__ __forceinline__ void mma_tf32(float c[4], const uint32_t a[4], const uint32_t b[2]) {
    asm volatile(
        "mma.sync.aligned.m16n8k8.row.col.f32.tf32.tf32.f32 "
        "{%0,%1,%2,%3}, {%4,%5,%6,%7}, {%8,%9}, {%0,%1,%2,%3};\n"
        : "+f"(c[0]), "+f"(c[1]), "+f"(c[2]), "+f"(c[3])
        : "r"(a[0]), "r"(a[1]), "r"(a[2]), "r"(a[3]), "r"(b[0]), "r"(b[1]));
}

// ---------------- Kernel A: QKV projection (tf32 mma) + window partition ----------------
// C[o,p] = sum_k W[o,k] x[n,k,p] + b[o].  Block tile 128x128, warp tile 64x32.
__global__ __launch_bounds__(256, 2)
void qkv_kernel(const float* __restrict__ x,
                const float* __restrict__ Wq, const float* __restrict__ bq,
                const float* __restrict__ Wk, const float* __restrict__ bk,
                const float* __restrict__ Wv, const float* __restrict__ bv) {
    __shared__ float As[128][36];   // [o][k] pad 36
    __shared__ float Bs[32][136];   // [k][p] pad 136

    int z = blockIdx.z;
    int n = z & 3;
    int which = z >> 2;
    const float* W = (which == 0) ? Wq : (which == 1) ? Wk : Wv;
    const float* bvec = (which == 0) ? bq : (which == 1) ? bk : bv;
    int h = blockIdx.y;
    int p_base = blockIdx.x * 128;
    const float* xn = x + (size_t)n * DIM * PPTS;

    int tid = threadIdx.x, lane = tid & 31, wid = tid >> 5;
    int g = lane >> 2, t = lane & 3;
    int m0w = (wid >> 2) * 64, n0w = (wid & 3) * 32;

    float acc[4][4][4] = {};

    for (int k0 = 0; k0 < 128; k0 += 32) {
        #pragma unroll
        for (int r = 0; r < 4; r++) {
            int idx = tid + r * 256;
            int oo = idx >> 3, qq = idx & 7;
            float4 w4 = *(const float4*)&W[(size_t)(h * 128 + oo) * 128 + k0 + qq * 4];
            float4 c4 = make_float4(tf32f(w4.x), tf32f(w4.y), tf32f(w4.z), tf32f(w4.w));
            *(float4*)&As[oo][qq * 4] = c4;
        }
        #pragma unroll
        for (int r = 0; r < 4; r++) {
            int idx = tid + r * 256;
            int kk = idx >> 5, pq = idx & 31;
            float4 x4 = *(const float4*)&xn[(size_t)(k0 + kk) * PPTS + p_base + pq * 4];
            float4 c4 = make_float4(tf32f(x4.x), tf32f(x4.y), tf32f(x4.z), tf32f(x4.w));
            *(float4*)&Bs[kk][pq * 4] = c4;
        }
        __syncthreads();
        #pragma unroll
        for (int ks = 0; ks < 4; ks++) {
            uint32_t af[4][4], bf[4][2];
            #pragma unroll
            for (int mf = 0; mf < 4; mf++) {
                int m = m0w + mf * 16;
                af[mf][0] = __float_as_uint(As[m + g][ks * 8 + t]);
                af[mf][1] = __float_as_uint(As[m + g + 8][ks * 8 + t]);
                af[mf][2] = __float_as_uint(As[m + g][ks * 8 + t + 4]);
                af[mf][3] = __float_as_uint(As[m + g + 8][ks * 8 + t + 4]);
            }
            #pragma unroll
            for (int nf = 0; nf < 4; nf++) {
                int nn = n0w + nf * 8 + g;
                bf[nf][0] = __float_as_uint(Bs[ks * 8 + t][nn]);
                bf[nf][1] = __float_as_uint(Bs[ks * 8 + t + 4][nn]);
            }
            #pragma unroll
            for (int mf = 0; mf < 4; mf++)
                #pragma unroll
                for (int nf = 0; nf < 4; nf++)
                    mma_tf32(acc[mf][nf], af[mf], bf[nf]);
        }
        __syncthreads();
    }

    // epilogue: scatter to window layouts
    float biasr[4][2];
    #pragma unroll
    for (int mf = 0; mf < 4; mf++)
        #pragma unroll
        for (int rs = 0; rs < 2; rs++)
            biasr[mf][rs] = bvec[h * 128 + m0w + mf * 16 + rs * 8 + g];

    size_t headbase = ((size_t)n * HEADS + h) * WN;

    #pragma unroll
    for (int nf = 0; nf < 4; nf++) {
        #pragma unroll
        for (int cs = 0; cs < 2; cs++) {
            int p = p_base + n0w + nf * 8 + 2 * t + cs;
            int pr = p / CWID, pc = p - pr * CWID;
            int win = (pr / WIN) * NWX + (pc / WIN);
            int tok = (pr % WIN) * WIN + (pc % WIN);
            if (which < 2) {
                float* base = (which == 0 ? g_q : g_k) + (headbase + win) * (DIM * PTP) + tok;
                #pragma unroll
                for (int mf = 0; mf < 4; mf++)
                    #pragma unroll
                    for (int rs = 0; rs < 2; rs++) {
                        int d = m0w + mf * 16 + rs * 8 + g;
                        base[(size_t)d * PTP] = acc[mf][nf][rs * 2 + cs] + biasr[mf][rs];
                    }
            } else {
                float* base = g_v + ((headbase + win) * PT + tok) * DIM;
                #pragma unroll
                for (int mf = 0; mf < 4; mf++)
                    #pragma unroll
                    for (int rs = 0; rs < 2; rs++) {
                        int d = m0w + mf * 16 + rs * 8 + g;
                        base[d] = acc[mf][nf][rs * 2 + cs] + biasr[mf][rs];
                    }
            }
        }
    }
}

// ---------------- Kernel B: windowed attention (fp32, conflict-free) ----------------
#define VROW 132
__global__ __launch_bounds__(256, 2)
void attn_kernel(const float* __restrict__ pos_code) {
    extern __shared__ float sm[];
    float* sqT = sm;                        // [128][PTP]
    float* skT = sqT + DIM * PTP;           // [128][PTP]
    float* sv  = skT + DIM * PTP;           // [49][VROW]
    float* S   = sv + PT * VROW;            // [52][52]
    float* sb  = S + PTP * PTP;             // [169]

    int bid = blockIdx.x;
    int w = bid & 255;
    int h = (bid >> 8) & 7;
    int n = bid >> 11;
    int tid = threadIdx.x;

    size_t base = ((size_t)n * HEADS + h) * WN + w;
    const float4* gq4 = (const float4*)(g_q + base * (DIM * PTP));
    const float4* gk4 = (const float4*)(g_k + base * (DIM * PTP));
    const float4* gv4 = (const float4*)(g_v + base * (PT * DIM));

    for (int i = tid; i < DIM * PTP / 4; i += 256) {
        ((float4*)sqT)[i] = gq4[i];
        ((float4*)skT)[i] = gk4[i];
    }
    for (int i = tid; i < PT * 32; i += 256) {
        int r = i >> 5, c = i & 31;
        ((float4*)(sv + r * VROW))[c] = gv4[i];
    }
    for (int i = tid; i < 169; i += 256) sb[i] = pos_code[i * HEADS + h];
    __syncthreads();

    // ---- QK: outer-product over d; thread tile 4(j) x 4(i) ----
    const float scale = 0.08838834764831845f;
    if (tid < 169) {
        int tj = tid / 13, ti = tid - tj * 13;
        int j0 = tj * 4, i0 = ti * 4;
        float a[4][4] = {};
        #pragma unroll 4
        for (int d = 0; d < DIM; d++) {
            float4 qv = *(const float4*)&sqT[d * PTP + j0];
            float4 kv = *(const float4*)&skT[d * PTP + i0];
            float qa[4] = {qv.x, qv.y, qv.z, qv.w};
            float ka[4] = {kv.x, kv.y, kv.z, kv.w};
            #pragma unroll
            for (int jj = 0; jj < 4; jj++)
                #pragma unroll
                for (int ii = 0; ii < 4; ii++)
                    a[jj][ii] += qa[jj] * ka[ii];
        }
        #pragma unroll
        for (int jj = 0; jj < 4; jj++) {
            int j = j0 + jj;
            int yj = j / WIN, xj = j - yj * WIN;
            #pragma unroll
            for (int ii = 0; ii < 4; ii++) {
                int i = i0 + ii;
                int yi = i / WIN, xi = i - yi * WIN;
                int ridx = (yi - yj + WIN - 1) + (xi - xj + WIN - 1) * (2 * WIN - 1);
                ridx = min(168, max(0, ridx));
                S[j * PTP + i] = a[jj][ii] * scale + sb[ridx];
            }
        }
    }
    __syncthreads();

    // ---- softmax over i (rows j), warp-parallel ----
    {
        int warp = tid >> 5, lane = tid & 31;
        for (int j = warp; j < PT; j += 8) {
            float* row = S + j * PTP;
            float v0 = row[lane];
            float v1 = (lane + 32 < PT) ? row[lane + 32] : -1e30f;
            float m = fmaxf(v0, v1);
            #pragma unroll
            for (int off = 16; off; off >>= 1)
                m = fmaxf(m, __shfl_xor_sync(0xffffffffu, m, off));
            float e0 = __expf(v0 - m);
            float e1 = (lane + 32 < PT) ? __expf(v1 - m) : 0.f;
            float s = e0 + e1;
            #pragma unroll
            for (int off = 16; off; off >>= 1)
                s += __shfl_xor_sync(0xffffffffu, s, off);
            float inv = 1.f / s;
            row[lane] = e0 * inv;
            if (lane + 32 < PT) row[lane + 32] = e1 * inv;
        }
    }
    __syncthreads();

    // ---- PV: out[d][j] = sum_i v[i][d] * P[j][i] ----
    int wy = w >> 4, wx = w & 15;
    float* mid = g_mid + ((size_t)n * (HEADS * DIM) + h * DIM) * PPTS;
    for (int tt = tid; tt < 13 * 32; tt += 256) {
        int jq = tt >> 5, dq = tt & 31;
        int j0 = jq * 4;
        float4 a0 = make_float4(0.f, 0.f, 0.f, 0.f), a1 = a0, a2 = a0, a3 = a0;
        #pragma unroll 7
        for (int i = 0; i < PT; i++) {
            float4 vv = *(const float4*)&sv[i * VROW + dq * 4];
            float p0 = S[(j0 + 0) * PTP + i], p1 = S[(j0 + 1) * PTP + i];
            float p2 = S[(j0 + 2) * PTP + i], p3 = S[(j0 + 3) * PTP + i];
            a0.x += vv.x * p0; a0.y += vv.y * p0; a0.z += vv.z * p0; a0.w += vv.w * p0;
            a1.x += vv.x * p1; a1.y += vv.y * p1; a1.z += vv.z * p1; a1.w += vv.w * p1;
            a2.x += vv.x * p2; a2.y += vv.y * p2; a2.z += vv.z * p2; a2.w += vv.w * p2;
            a3.x += vv.x * p3; a3.y += vv.y * p3; a3.z += vv.z * p3; a3.w += vv.w * p3;
        }
        float4 accs[4] = {a0, a1, a2, a3};
        int d0 = dq * 4;
        #pragma unroll
        for (int jj = 0; jj < 4; jj++) {
            int j = j0 + jj;
            if (j >= PT) break;
            int jy = j / WIN, jx = j - jy * WIN;
            int p = (wy * WIN + jy) * CWID + wx * WIN + jx;
            mid[(size_t)(d0 + 0) * PPTS + p] = accs[jj].x;
            mid[(size_t)(d0 + 1) * PPTS + p] = accs[jj].y;
            mid[(size_t)(d0 + 2) * PPTS + p] = accs[jj].z;
            mid[(size_t)(d0 + 3) * PPTS + p] = accs[jj].w;
        }
    }
}

// ---------------- Kernel C: output projection (tf32 mma) ----------------
// out[n,o,p] = sum_c Wo[o,c] mid[n,c,p] + bo[o]; M=128, K=1024
__global__ __launch_bounds__(256, 2)
void out_kernel(const float* __restrict__ Wo, const float* __restrict__ bo,
                float* __restrict__ out) {
    __shared__ float As[128][36];
    __shared__ float Bs[32][136];

    int n = blockIdx.z;
    int p_base = blockIdx.x * 128;
    const float* mid = g_mid + (size_t)n * (HEADS * DIM) * PPTS;

    int tid = threadIdx.x, lane = tid & 31, wid = tid >> 5;
    int g = lane >> 2, t = lane & 3;
    int m0w = (wid >> 2) * 64, n0w = (wid & 3) * 32;

    float acc[4][4][4] = {};

    for (int k0 = 0; k0 < 1024; k0 += 32) {
        #pragma unroll
        for (int r = 0; r < 4; r++) {
            int idx = tid + r * 256;
            int oo = idx >> 3, qq = idx & 7;
            float4 w4 = *(const float4*)&Wo[(size_t)oo * 1024 + k0 + qq * 4];
            float4 c4 = make_float4(tf32f(w4.x), tf32f(w4.y), tf32f(w4.z), tf32f(w4.w));
            *(float4*)&As[oo][qq * 4] = c4;
        }
        #pragma unroll
        for (int r = 0; r < 4; r++) {
            int idx = tid + r * 256;
            int kk = idx >> 5, pq = idx & 31;
            float4 x4 = *(const float4*)&mid[(size_t)(k0 + kk) * PPTS + p_base + pq * 4];
            float4 c4 = make_float4(tf32f(x4.x), tf32f(x4.y), tf32f(x4.z), tf32f(x4.w));
            *(float4*)&Bs[kk][pq * 4] = c4;
        }
        __syncthreads();
        #pragma unroll
        for (int ks = 0; ks < 4; ks++) {
            uint32_t af[4][4], bf[4][2];
            #pragma unroll
            for (int mf = 0; mf < 4; mf++) {
                int m = m0w + mf * 16;
                af[mf][0] = __float_as_uint(As[m + g][ks * 8 + t]);
                af[mf][1] = __float_as_uint(As[m + g + 8][ks * 8 + t]);
                af[mf][2] = __float_as_uint(As[m + g][ks * 8 + t + 4]);
                af[mf][3] = __float_as_uint(As[m + g + 8][ks * 8 + t + 4]);
            }
            #pragma unroll
            for (int nf = 0; nf < 4; nf++) {
                int nn = n0w + nf * 8 + g;
                bf[nf][0] = __float_as_uint(Bs[ks * 8 + t][nn]);
                bf[nf][1] = __float_as_uint(Bs[ks * 8 + t + 4][nn]);
            }
            #pragma unroll
            for (int mf = 0; mf < 4; mf++)
                #pragma unroll
                for (int nf = 0; nf < 4; nf++)
                    mma_tf32(acc[mf][nf], af[mf], bf[nf]);
        }
        __syncthreads();
    }

    #pragma unroll
    for (int mf = 0; mf < 4; mf++) {
        #pragma unroll
        for (int rs = 0; rs < 2; rs++) {
            int o = m0w + mf * 16 + rs * 8 + g;
            float bias = bo[o];
            float* dst = out + ((size_t)n * DIM + o) * PPTS;
            #pragma unroll
            for (int nf = 0; nf < 4; nf++) {
                int p = p_base + n0w + nf * 8 + 2 * t;
                float2 v = make_float2(acc[mf][nf][rs * 2 + 0] + bias,
                                       acc[mf][nf][rs * 2 + 1] + bias);
                *(float2*)&dst[p] = v;
            }
        }
    }
}

// ---------------- launch ----------------
extern "C" void kernel_launch(void* const* d_in, const int* in_sizes, int n_in,
                              void* d_out, int out_size) {
    const float* x   = (const float*)d_in[0];
    const float* Wq  = (const float*)d_in[1];
    const float* bq  = (const float*)d_in[2];
    const float* Wk  = (const float*)d_in[3];
    const float* bk  = (const float*)d_in[4];
    const float* Wv  = (const float*)d_in[5];
    const float* bv  = (const float*)d_in[6];
    const float* Wo  = (const float*)d_in[7];
    const float* bo  = (const float*)d_in[8];
    const float* pos = (const float*)d_in[9];
    float* out = (float*)d_out;

    {
        dim3 grid(PPTS / 128, HEADS, 12);
        qkv_kernel<<<grid, 256>>>(x, Wq, bq, Wk, bk, Wv, bv);
    }
    {
        const int smem = (2 * DIM * PTP + PT * VROW + PTP * PTP + 169) * (int)sizeof(float);
        static int attr_set = 0;
        if (!attr_set) {
            cudaFuncSetAttribute(attn_kernel, cudaFuncAttributeMaxDynamicSharedMemorySize, smem);
            attr_set = 1;
        }
        attn_kernel<<<NB * HEADS * WN, 256, smem>>>(pos);
    }
    {
        dim3 grid(PPTS / 128, 1, NB);
        out_kernel<<<grid, 256>>>(Wo, bo, out);
    }
}

// round 4
// speedup vs baseline: 6.3154x; 1.7224x over previous
#include <cuda_runtime.h>
#include <cuda_bf16.h>
#include <cstdint>

// ---------------- problem constants ----------------
#define NB    4
#define DIM   128
#define HEADS 8
#define PPTS  12544
#define CWID  112
#define WIN   7
#define NWX   16
#define WN    256
#define PT    49

// q,k,v: [n][h][win][tok=49][d=128], values pre-rounded to tf32
__device__ float g_q[(size_t)NB * HEADS * WN * PT * DIM];
__device__ float g_k[(size_t)NB * HEADS * WN * PT * DIM];
__device__ float g_v[(size_t)NB * HEADS * WN * PT * DIM];
__device__ float g_mid[(size_t)NB * HEADS * DIM * PPTS];

__device__ __forceinline__ float tf32f(float x) {
    uint32_t u;
    asm("cvt.rna.tf32.f32 %0, %1;" : "=r"(u) : "f"(x));
    return __uint_as_float(u);
}
__device__ __forceinline__ uint32_t tf32u(float x) {
    uint32_t u;
    asm("cvt.rna.tf32.f32 %0, %1;" : "=r"(u) : "f"(x));
    return u;
}

__device__ __forceinline__ void mma_tf32(float c[4], const uint32_t a[4], const uint32_t b[2]) {
    asm volatile(
        "mma.sync.aligned.m16n8k8.row.col.f32.tf32.tf32.f32 "
        "{%0,%1,%2,%3}, {%4,%5,%6,%7}, {%8,%9}, {%0,%1,%2,%3};\n"
        : "+f"(c[0]), "+f"(c[1]), "+f"(c[2]), "+f"(c[3])
        : "r"(a[0]), "r"(a[1]), "r"(a[2]), "r"(a[3]), "r"(b[0]), "r"(b[1]));
}

// ---------------- Kernel A: QKV projection (tf32 mma) + window partition ----------------
__global__ __launch_bounds__(256, 2)
void qkv_kernel(const float* __restrict__ x,
                const float* __restrict__ Wq, const float* __restrict__ bq,
                const float* __restrict__ Wk, const float* __restrict__ bk,
                const float* __restrict__ Wv, const float* __restrict__ bv) {
    __shared__ float As[128][36];   // [o][k]
    __shared__ float Bs[32][136];   // [k][p]

    int z = blockIdx.z;
    int n = z & 3;
    int which = z >> 2;
    const float* W = (which == 0) ? Wq : (which == 1) ? Wk : Wv;
    const float* bvec = (which == 0) ? bq : (which == 1) ? bk : bv;
    float* garr = (which == 0) ? g_q : (which == 1) ? g_k : g_v;
    int h = blockIdx.y;
    int p_base = blockIdx.x * 128;
    const float* xn = x + (size_t)n * DIM * PPTS;

    int tid = threadIdx.x, lane = tid & 31, wid = tid >> 5;
    int g = lane >> 2, t = lane & 3;
    int m0w = (wid >> 2) * 64, n0w = (wid & 3) * 32;

    float acc[4][4][4] = {};

    for (int k0 = 0; k0 < 128; k0 += 32) {
        #pragma unroll
        for (int r = 0; r < 4; r++) {
            int idx = tid + r * 256;
            int oo = idx >> 3, qq = idx & 7;
            float4 w4 = *(const float4*)&W[(size_t)(h * 128 + oo) * 128 + k0 + qq * 4];
            float4 c4 = make_float4(tf32f(w4.x), tf32f(w4.y), tf32f(w4.z), tf32f(w4.w));
            *(float4*)&As[oo][qq * 4] = c4;
        }
        #pragma unroll
        for (int r = 0; r < 4; r++) {
            int idx = tid + r * 256;
            int kk = idx >> 5, pq = idx & 31;
            float4 x4 = *(const float4*)&xn[(size_t)(k0 + kk) * PPTS + p_base + pq * 4];
            float4 c4 = make_float4(tf32f(x4.x), tf32f(x4.y), tf32f(x4.z), tf32f(x4.w));
            *(float4*)&Bs[kk][pq * 4] = c4;
        }
        __syncthreads();
        #pragma unroll
        for (int ks = 0; ks < 4; ks++) {
            uint32_t af[4][4], bf[4][2];
            #pragma unroll
            for (int mf = 0; mf < 4; mf++) {
                int m = m0w + mf * 16;
                af[mf][0] = __float_as_uint(As[m + g][ks * 8 + t]);
                af[mf][1] = __float_as_uint(As[m + g + 8][ks * 8 + t]);
                af[mf][2] = __float_as_uint(As[m + g][ks * 8 + t + 4]);
                af[mf][3] = __float_as_uint(As[m + g + 8][ks * 8 + t + 4]);
            }
            #pragma unroll
            for (int nf = 0; nf < 4; nf++) {
                int nn = n0w + nf * 8 + g;
                bf[nf][0] = __float_as_uint(Bs[ks * 8 + t][nn]);
                bf[nf][1] = __float_as_uint(Bs[ks * 8 + t + 4][nn]);
            }
            #pragma unroll
            for (int mf = 0; mf < 4; mf++)
                #pragma unroll
                for (int nf = 0; nf < 4; nf++)
                    mma_tf32(acc[mf][nf], af[mf], bf[nf]);
        }
        __syncthreads();
    }

    float biasr[4][2];
    #pragma unroll
    for (int mf = 0; mf < 4; mf++)
        #pragma unroll
        for (int rs = 0; rs < 2; rs++)
            biasr[mf][rs] = bvec[h * 128 + m0w + mf * 16 + rs * 8 + g];

    size_t headbase = ((size_t)n * HEADS + h) * WN;

    // coalesced scalar stores: per (nf,cs,mf,rs) warp writes 4 toks x 8 consecutive d
    #pragma unroll
    for (int nf = 0; nf < 4; nf++) {
        #pragma unroll
        for (int cs = 0; cs < 2; cs++) {
            int p = p_base + n0w + nf * 8 + 2 * t + cs;
            int pr = p / CWID, pc = p - pr * CWID;
            int win = (pr / WIN) * NWX + (pc / WIN);
            int tok = (pr % WIN) * WIN + (pc % WIN);
            float* base = garr + ((headbase + win) * PT + tok) * DIM;
            #pragma unroll
            for (int mf = 0; mf < 4; mf++)
                #pragma unroll
                for (int rs = 0; rs < 2; rs++) {
                    int d = m0w + mf * 16 + rs * 8 + g;
                    base[d] = tf32f(acc[mf][nf][rs * 2 + cs] + biasr[mf][rs]);
                }
        }
    }
}

// ---------------- Kernel B: windowed attention (tf32 mma) ----------------
// smem layout (floats):
//   sq [64][132]   @ 0        (also aliased by so[128][52] in final stage)
//   sk [56][132]   @ 8448
//   sv [56][132]   @ 15840    (rows 49..55 zeroed)
//   S  [64][56]    @ 23232
//   sb [169]       @ 26816
#define SQ_OFF 0
#define SK_OFF 8448
#define SV_OFF 15840
#define SS_OFF 23232
#define SB_OFF 26816
#define SM_FLOATS 26985

__global__ __launch_bounds__(256, 2)
void attn_kernel(const float* __restrict__ pos_code) {
    extern __shared__ float sm[];
    float* sq = sm + SQ_OFF;
    float* sk = sm + SK_OFF;
    float* sv = sm + SV_OFF;
    float* S  = sm + SS_OFF;
    float* sb = sm + SB_OFF;
    float* so = sm;            // [128][52], aliases sq

    int bid = blockIdx.x;
    int w = bid & 255;
    int h = (bid >> 8) & 7;
    int n = bid >> 11;
    int tid = threadIdx.x, lane = tid & 31, wid = tid >> 5;
    int g = lane >> 2, t = lane & 3;

    size_t base = (((size_t)n * HEADS + h) * WN + w) * (PT * DIM);
    const float4* gq4 = (const float4*)(g_q + base);
    const float4* gk4 = (const float4*)(g_k + base);
    const float4* gv4 = (const float4*)(g_v + base);

    for (int i = tid; i < PT * 32; i += 256) {
        int r = i >> 5, c = i & 31;
        ((float4*)(sq + r * 132))[c] = gq4[i];
        ((float4*)(sk + r * 132))[c] = gk4[i];
        ((float4*)(sv + r * 132))[c] = gv4[i];
    }
    for (int i = tid; i < 7 * 132; i += 256) sv[49 * 132 + i] = 0.f;   // zero pad rows
    for (int i = tid; i < 169; i += 256) sb[i] = pos_code[i * HEADS + h];
    __syncthreads();

    // ---- QK: S[j][i] = sum_d q[j][d] k[i][d] ; m=64(j), n=56(i), k=128 ----
    int m0 = (wid >> 1) * 16;
    int ng = wid & 1;
    {
        float acc[4][4] = {};
        #pragma unroll
        for (int ks = 0; ks < 16; ks++) {
            int k0 = ks * 8;
            uint32_t a[4];
            a[0] = __float_as_uint(sq[(m0 + g) * 132 + k0 + t]);
            a[1] = __float_as_uint(sq[(m0 + g + 8) * 132 + k0 + t]);
            a[2] = __float_as_uint(sq[(m0 + g) * 132 + k0 + t + 4]);
            a[3] = __float_as_uint(sq[(m0 + g + 8) * 132 + k0 + t + 4]);
            #pragma unroll
            for (int nt = 0; nt < 4; nt++) {
                int nti = ng * 4 + nt;
                if (nti >= 7) break;
                int n0 = nti * 8;
                uint32_t b[2];
                b[0] = __float_as_uint(sk[(n0 + g) * 132 + k0 + t]);
                b[1] = __float_as_uint(sk[(n0 + g) * 132 + k0 + t + 4]);
                mma_tf32(acc[nt], a, b);
            }
        }
        #pragma unroll
        for (int nt = 0; nt < 4; nt++) {
            int nti = ng * 4 + nt;
            if (nti >= 7) break;
            int n0 = nti * 8;
            S[(m0 + g) * 56 + n0 + 2 * t]     = acc[nt][0];
            S[(m0 + g) * 56 + n0 + 2 * t + 1] = acc[nt][1];
            S[(m0 + g + 8) * 56 + n0 + 2 * t]     = acc[nt][2];
            S[(m0 + g + 8) * 56 + n0 + 2 * t + 1] = acc[nt][3];
        }
    }
    __syncthreads();

    // ---- softmax over i per row j (scale + rel-pos bias), zero pad cols ----
    const float scale = 0.08838834764831845f;
    for (int j = wid; j < PT; j += 8) {
        int yj = j / WIN, xj = j - yj * WIN;
        float* row = S + j * 56;
        int i0 = lane;
        int y0 = i0 / WIN, x0 = i0 - y0 * WIN;
        int r0 = (y0 - yj + WIN - 1) + (x0 - xj + WIN - 1) * (2 * WIN - 1);
        float v0 = row[i0] * scale + sb[r0];
        float v1 = -1e30f;
        int i1 = lane + 32;
        if (i1 < PT) {
            int y1 = i1 / WIN, x1 = i1 - y1 * WIN;
            int r1 = (y1 - yj + WIN - 1) + (x1 - xj + WIN - 1) * (2 * WIN - 1);
            v1 = row[i1] * scale + sb[r1];
        }
        float m = fmaxf(v0, v1);
        #pragma unroll
        for (int off = 16; off; off >>= 1) m = fmaxf(m, __shfl_xor_sync(0xffffffffu, m, off));
        float e0 = __expf(v0 - m);
        float e1 = (i1 < PT) ? __expf(v1 - m) : 0.f;
        float s = e0 + e1;
        #pragma unroll
        for (int off = 16; off; off >>= 1) s += __shfl_xor_sync(0xffffffffu, s, off);
        float inv = 1.f / s;
        row[i0] = tf32f(e0 * inv);
        if (i1 < PT) row[i1] = tf32f(e1 * inv);
        else if (i1 < 56) row[i1] = 0.f;     // zero pad cols 49..55
    }
    __syncthreads();

    // ---- PV: O[j][d] = sum_i P[j][i] v[i][d]; m=64(j), n=128(d), k=56(i) ----
    float acc[8][4] = {};
    int dg = wid & 1;   // d half: 0 -> d 0..63, 1 -> 64..127
    #pragma unroll
    for (int ks = 0; ks < 7; ks++) {
        int k0 = ks * 8;
        uint32_t a[4];
        a[0] = __float_as_uint(S[(m0 + g) * 56 + k0 + t]);
        a[1] = __float_as_uint(S[(m0 + g + 8) * 56 + k0 + t]);
        a[2] = __float_as_uint(S[(m0 + g) * 56 + k0 + t + 4]);
        a[3] = __float_as_uint(S[(m0 + g + 8) * 56 + k0 + t + 4]);
        #pragma unroll
        for (int nt = 0; nt < 8; nt++) {
            int n0 = (dg * 8 + nt) * 8;
            uint32_t b[2];
            b[0] = __float_as_uint(sv[(k0 + t) * 132 + n0 + g]);
            b[1] = __float_as_uint(sv[(k0 + t + 4) * 132 + n0 + g]);
            mma_tf32(acc[nt], a, b);
        }
    }
    __syncthreads();   // done reading sq region? (sq unused since QK); ensure all warps past softmax/PV reads of S before so writes? so doesn't alias S -- alias sq only. Sync guards stage ordering.

    // stage O into so[d][tok]
    int j1 = m0 + g, j2 = m0 + g + 8;
    #pragma unroll
    for (int nt = 0; nt < 8; nt++) {
        int d0 = (dg * 8 + nt) * 8 + 2 * t;
        if (j1 < PT) {
            so[d0 * 52 + j1] = acc[nt][0];
            so[(d0 + 1) * 52 + j1] = acc[nt][1];
        }
        if (j2 < PT) {
            so[d0 * 52 + j2] = acc[nt][2];
            so[(d0 + 1) * 52 + j2] = acc[nt][3];
        }
    }
    __syncthreads();

    // coalesced-ish write to g_mid[n][h*128+d][p]
    int wy = w >> 4, wx = w & 15;
    float* mid = g_mid + ((size_t)n * (HEADS * DIM) + h * DIM) * PPTS
               + (size_t)(wy * WIN) * CWID + wx * WIN;
    for (int d = wid; d < DIM; d += 8) {
        float* dst = mid + (size_t)d * PPTS;
        int i = lane;
        dst[(i / 7) * CWID + i % 7] = so[d * 52 + i];
        int i2 = lane + 32;
        if (i2 < PT) dst[(i2 / 7) * CWID + i2 % 7] = so[d * 52 + i2];
    }
}

// ---------------- Kernel C: output projection (tf32 mma) ----------------
__global__ __launch_bounds__(256, 2)
void out_kernel(const float* __restrict__ Wo, const float* __restrict__ bo,
                float* __restrict__ out) {
    __shared__ float As[128][36];
    __shared__ float Bs[32][136];

    int n = blockIdx.z;
    int p_base = blockIdx.x * 128;
    const float* mid = g_mid + (size_t)n * (HEADS * DIM) * PPTS;

    int tid = threadIdx.x, lane = tid & 31, wid = tid >> 5;
    int g = lane >> 2, t = lane & 3;
    int m0w = (wid >> 2) * 64, n0w = (wid & 3) * 32;

    float acc[4][4][4] = {};

    for (int k0 = 0; k0 < 1024; k0 += 32) {
        #pragma unroll
        for (int r = 0; r < 4; r++) {
            int idx = tid + r * 256;
            int oo = idx >> 3, qq = idx & 7;
            float4 w4 = *(const float4*)&Wo[(size_t)oo * 1024 + k0 + qq * 4];
            float4 c4 = make_float4(tf32f(w4.x), tf32f(w4.y), tf32f(w4.z), tf32f(w4.w));
            *(float4*)&As[oo][qq * 4] = c4;
        }
        #pragma unroll
        for (int r = 0; r < 4; r++) {
            int idx = tid + r * 256;
            int kk = idx >> 5, pq = idx & 31;
            float4 x4 = *(const float4*)&mid[(size_t)(k0 + kk) * PPTS + p_base + pq * 4];
            float4 c4 = make_float4(tf32f(x4.x), tf32f(x4.y), tf32f(x4.z), tf32f(x4.w));
            *(float4*)&Bs[kk][pq * 4] = c4;
        }
        __syncthreads();
        #pragma unroll
        for (int ks = 0; ks < 4; ks++) {
            uint32_t af[4][4], bf[4][2];
            #pragma unroll
            for (int mf = 0; mf < 4; mf++) {
                int m = m0w + mf * 16;
                af[mf][0] = __float_as_uint(As[m + g][ks * 8 + t]);
                af[mf][1] = __float_as_uint(As[m + g + 8][ks * 8 + t]);
                af[mf][2] = __float_as_uint(As[m + g][ks * 8 + t + 4]);
                af[mf][3] = __float_as_uint(As[m + g + 8][ks * 8 + t + 4]);
            }
            #pragma unroll
            for (int nf = 0; nf < 4; nf++) {
                int nn = n0w + nf * 8 + g;
                bf[nf][0] = __float_as_uint(Bs[ks * 8 + t][nn]);
                bf[nf][1] = __float_as_uint(Bs[ks * 8 + t + 4][nn]);
            }
            #pragma unroll
            for (int mf = 0; mf < 4; mf++)
                #pragma unroll
                for (int nf = 0; nf < 4; nf++)
                    mma_tf32(acc[mf][nf], af[mf], bf[nf]);
        }
        __syncthreads();
    }

    #pragma unroll
    for (int mf = 0; mf < 4; mf++) {
        #pragma unroll
        for (int rs = 0; rs < 2; rs++) {
            int o = m0w + mf * 16 + rs * 8 + g;
            float bias = bo[o];
            float* dst = out + ((size_t)n * DIM + o) * PPTS;
            #pragma unroll
            for (int nf = 0; nf < 4; nf++) {
                int p = p_base + n0w + nf * 8 + 2 * t;
                float2 v = make_float2(acc[mf][nf][rs * 2 + 0] + bias,
                                       acc[mf][nf][rs * 2 + 1] + bias);
                *(float2*)&dst[p] = v;
            }
        }
    }
}

// ---------------- launch ----------------
extern "C" void kernel_launch(void* const* d_in, const int* in_sizes, int n_in,
                              void* d_out, int out_size) {
    const float* x   = (const float*)d_in[0];
    const float* Wq  = (const float*)d_in[1];
    const float* bq  = (const float*)d_in[2];
    const float* Wk  = (const float*)d_in[3];
    const float* bk  = (const float*)d_in[4];
    const float* Wv  = (const float*)d_in[5];
    const float* bv  = (const float*)d_in[6];
    const float* Wo  = (const float*)d_in[7];
    const float* bo  = (const float*)d_in[8];
    const float* pos = (const float*)d_in[9];
    float* out = (float*)d_out;

    {
        dim3 grid(PPTS / 128, HEADS, 12);
        qkv_kernel<<<grid, 256>>>(x, Wq, bq, Wk, bk, Wv, bv);
    }
    {
        const int smem = SM_FLOATS * (int)sizeof(float);   // ~105.4 KB
        static int attr_set = 0;
        if (!attr_set) {
            cudaFuncSetAttribute(attn_kernel, cudaFuncAttributeMaxDynamicSharedMemorySize, smem);
            attr_set = 1;
        }
        attn_kernel<<<NB * HEADS * WN, 256, smem>>>(pos);
    }
    {
        dim3 grid(PPTS / 128, 1, NB);
        out_kernel<<<grid, 256>>>(Wo, bo, out);
    }
}